// round 3
// baseline (speedup 1.0000x reference)
#include <cuda_runtime.h>
#include <cuda_bf16.h>
#include <cstdint>

// Problem constants
#define B_   2
#define S_   2048
#define H_   16
#define DH_  64
#define DM_  1024
#define M_   (B_ * S_)          // 4096 rows

// Scratch (device globals; allocation-free rule)
__device__ float g_q[M_ * DM_];
__device__ float g_k[M_ * DM_];
__device__ float g_v[M_ * DM_];
__device__ float g_vsuf[M_ * DM_];
__device__ float g_z[M_ * DM_];

// ---------------------------------------------------------------------------
// SGEMM: C[M,1024] = A[M,1024] * B + bias, 128x128x8 tiling, 8x8 per thread.
// mode 0: B element (k, n) at W[(n>>6)*65536 + k*64 + (n&63)]  (QKV weights [H,DM,DH])
// mode 1: B element (k, n) at W[k*1024 + n]                    (W_O [H*DH, DM])
// ---------------------------------------------------------------------------
__global__ __launch_bounds__(256)
void sgemm_bias(const float* __restrict__ A, const float* __restrict__ Bw,
                const float* __restrict__ bias, float* __restrict__ C, int mode)
{
    __shared__ float As[8][132];
    __shared__ float Bs[8][128];

    const int m0 = blockIdx.x * 128;
    const int n0 = blockIdx.y * 128;
    const int t  = threadIdx.x;
    const int ty = t >> 4, tx = t & 15;

    float acc[8][8];
#pragma unroll
    for (int i = 0; i < 8; i++)
#pragma unroll
        for (int j = 0; j < 8; j++) acc[i][j] = 0.f;

    const int am = t >> 1;          // 0..127
    const int ak = (t & 1) * 4;     // 0 or 4
    const int bk = t >> 5;          // 0..7
    const int bn = (t & 31) * 4;    // 0..124
    const float* Aptr = A + (size_t)(m0 + am) * 1024 + ak;
    const int nb = n0 + bn;

    for (int k0 = 0; k0 < 1024; k0 += 8) {
        float4 av = *(const float4*)(Aptr + k0);
        size_t baddr;
        if (mode == 0) baddr = (size_t)(nb >> 6) * 65536 + (size_t)(k0 + bk) * 64 + (nb & 63);
        else           baddr = (size_t)(k0 + bk) * 1024 + nb;
        float4 bv = *(const float4*)(Bw + baddr);

        __syncthreads();
        As[ak + 0][am] = av.x;
        As[ak + 1][am] = av.y;
        As[ak + 2][am] = av.z;
        As[ak + 3][am] = av.w;
        *(float4*)&Bs[bk][bn] = bv;
        __syncthreads();

#pragma unroll
        for (int kk = 0; kk < 8; kk++) {
            float4 a0 = *(float4*)&As[kk][ty * 8];
            float4 a1 = *(float4*)&As[kk][ty * 8 + 4];
            float4 b0 = *(float4*)&Bs[kk][tx * 8];
            float4 b1 = *(float4*)&Bs[kk][tx * 8 + 4];
            float a[8] = {a0.x, a0.y, a0.z, a0.w, a1.x, a1.y, a1.z, a1.w};
            float b[8] = {b0.x, b0.y, b0.z, b0.w, b1.x, b1.y, b1.z, b1.w};
#pragma unroll
            for (int i = 0; i < 8; i++)
#pragma unroll
                for (int j = 0; j < 8; j++) acc[i][j] = fmaf(a[i], b[j], acc[i][j]);
        }
    }

    float bb[8];
#pragma unroll
    for (int j = 0; j < 8; j++) bb[j] = bias[n0 + tx * 8 + j];

#pragma unroll
    for (int i = 0; i < 8; i++) {
        int row = m0 + ty * 8 + i;
        float* Crow = C + (size_t)row * 1024 + n0 + tx * 8;
        float4 o0 = {acc[i][0] + bb[0], acc[i][1] + bb[1], acc[i][2] + bb[2], acc[i][3] + bb[3]};
        float4 o1 = {acc[i][4] + bb[4], acc[i][5] + bb[5], acc[i][6] + bb[6], acc[i][7] + bb[7]};
        *(float4*)(Crow)     = o0;
        *(float4*)(Crow + 4) = o1;
    }
}

// ---------------------------------------------------------------------------
// V suffix sum: vsuf[b,q,h,d] = sum_{k>q} v[b,k,h,d]
// One block per (b,h): 512 threads = 8 chunks x 64 d, chunk length 256.
// ---------------------------------------------------------------------------
__global__ __launch_bounds__(512)
void vsuf_kernel(const float* __restrict__ v, float* __restrict__ vsuf)
{
    __shared__ float sums[8][64];
    const int bh = blockIdx.x;
    const int b = bh >> 4, h = bh & 15;
    const int d = threadIdx.x & 63;
    const int c = threadIdx.x >> 6;       // 0..7
    const int L = S_ / 8;                 // 256
    const int lo = c * L;

    auto idx = [&](int s) { return ((size_t)(b * S_ + s) * H_ + h) * DH_ + d; };

    float s = 0.f;
    for (int q = lo; q < lo + L; q++) s += v[idx(q)];
    sums[c][d] = s;
    __syncthreads();

    float off = 0.f;
    for (int cc = c + 1; cc < 8; cc++) off += sums[cc][d];

    float run = off;
    for (int q = lo + L - 1; q >= lo; q--) {
        vsuf[idx(q)] = run;
        run += v[idx(q)];
    }
}

// ---------------------------------------------------------------------------
// Flash attention (fp32) with masked-to-ZERO softmax semantics.
// Block: 64 q-rows of one (b,h). 256 threads (16x16), 4x4 register tiles.
// Dynamic smem: Qs/Ks/Vs/Ps each [64][68].
// ---------------------------------------------------------------------------
__global__ __launch_bounds__(256)
void flash_attn(const float* __restrict__ gq, const float* __restrict__ gk,
                const float* __restrict__ gv, const float* __restrict__ gvs,
                float* __restrict__ gz)
{
    extern __shared__ float sm[];
    float (*Qs)[68] = (float(*)[68])(sm);
    float (*Ks)[68] = (float(*)[68])(sm + 64 * 68);
    float (*Vs)[68] = (float(*)[68])(sm + 2 * 64 * 68);
    float (*Ps)[68] = (float(*)[68])(sm + 3 * 64 * 68);

    const int qt = blockIdx.x;
    const int bh = blockIdx.y;
    const int b = bh >> 4, h = bh & 15;
    const int q0 = qt * 64;
    const int t = threadIdx.x, ty = t >> 4, tx = t & 15;

    auto idx = [&](int s, int d) { return ((size_t)(b * S_ + s) * H_ + h) * DH_ + d; };

    const float scale = 0.125f;  // 1/sqrt(64)
    for (int i = t; i < 64 * 16; i += 256) {
        int r = i >> 4, c4 = (i & 15) * 4;
        float4 v = *(const float4*)&gq[idx(q0 + r, c4)];
        v.x *= scale; v.y *= scale; v.z *= scale; v.w *= scale;
        *(float4*)&Qs[r][c4] = v;
    }

    float m_i[4], l_i[4], acc[4][4];
#pragma unroll
    for (int i = 0; i < 4; i++) {
        m_i[i] = -1e30f; l_i[i] = 0.f;
#pragma unroll
        for (int j = 0; j < 4; j++) acc[i][j] = 0.f;
    }

    for (int kt = 0; kt <= qt; kt++) {
        const int k0 = kt * 64;
        __syncthreads();
        for (int i = t; i < 64 * 16; i += 256) {
            int r = i >> 4, c4 = (i & 15) * 4;
            *(float4*)&Ks[r][c4] = *(const float4*)&gk[idx(k0 + r, c4)];
            *(float4*)&Vs[r][c4] = *(const float4*)&gv[idx(k0 + r, c4)];
        }
        __syncthreads();

        float s[4][4];
#pragma unroll
        for (int i = 0; i < 4; i++)
#pragma unroll
            for (int j = 0; j < 4; j++) s[i][j] = 0.f;

#pragma unroll
        for (int d = 0; d < 64; d += 4) {
            float4 qa[4], ka[4];
#pragma unroll
            for (int i = 0; i < 4; i++) qa[i] = *(float4*)&Qs[ty * 4 + i][d];
#pragma unroll
            for (int j = 0; j < 4; j++) ka[j] = *(float4*)&Ks[tx * 4 + j][d];
#pragma unroll
            for (int i = 0; i < 4; i++)
#pragma unroll
                for (int j = 0; j < 4; j++) {
                    s[i][j] = fmaf(qa[i].x, ka[j].x, s[i][j]);
                    s[i][j] = fmaf(qa[i].y, ka[j].y, s[i][j]);
                    s[i][j] = fmaf(qa[i].z, ka[j].z, s[i][j]);
                    s[i][j] = fmaf(qa[i].w, ka[j].w, s[i][j]);
                }
        }

        if (kt == qt) {
#pragma unroll
            for (int i = 0; i < 4; i++)
#pragma unroll
                for (int j = 0; j < 4; j++)
                    if (k0 + tx * 4 + j > q0 + ty * 4 + i) s[i][j] = -1e30f;
        }

#pragma unroll
        for (int i = 0; i < 4; i++) {
            float mt = fmaxf(fmaxf(s[i][0], s[i][1]), fmaxf(s[i][2], s[i][3]));
#pragma unroll
            for (int off = 8; off >= 1; off >>= 1)
                mt = fmaxf(mt, __shfl_xor_sync(0xffffffffu, mt, off, 16));
            float mnew = fmaxf(m_i[i], mt);
            float rs = 0.f;
#pragma unroll
            for (int j = 0; j < 4; j++) {
                float p = __expf(s[i][j] - mnew);
                s[i][j] = p;
                rs += p;
            }
#pragma unroll
            for (int off = 8; off >= 1; off >>= 1)
                rs += __shfl_xor_sync(0xffffffffu, rs, off, 16);
            float corr = __expf(m_i[i] - mnew);
            l_i[i] = l_i[i] * corr + rs;
            m_i[i] = mnew;
#pragma unroll
            for (int j = 0; j < 4; j++) acc[i][j] *= corr;
            float4 pv = {s[i][0], s[i][1], s[i][2], s[i][3]};
            *(float4*)&Ps[ty * 4 + i][tx * 4] = pv;
        }
        __syncthreads();

#pragma unroll
        for (int kk = 0; kk < 64; kk += 4) {
            float4 pa[4], vb[4];
#pragma unroll
            for (int i = 0; i < 4; i++) pa[i] = *(float4*)&Ps[ty * 4 + i][kk];
#pragma unroll
            for (int u = 0; u < 4; u++) vb[u] = *(float4*)&Vs[kk + u][tx * 4];
#pragma unroll
            for (int i = 0; i < 4; i++) {
                acc[i][0] = fmaf(pa[i].x, vb[0].x, acc[i][0]);
                acc[i][1] = fmaf(pa[i].x, vb[0].y, acc[i][1]);
                acc[i][2] = fmaf(pa[i].x, vb[0].z, acc[i][2]);
                acc[i][3] = fmaf(pa[i].x, vb[0].w, acc[i][3]);
                acc[i][0] = fmaf(pa[i].y, vb[1].x, acc[i][0]);
                acc[i][1] = fmaf(pa[i].y, vb[1].y, acc[i][1]);
                acc[i][2] = fmaf(pa[i].y, vb[1].z, acc[i][2]);
                acc[i][3] = fmaf(pa[i].y, vb[1].w, acc[i][3]);
                acc[i][0] = fmaf(pa[i].z, vb[2].x, acc[i][0]);
                acc[i][1] = fmaf(pa[i].z, vb[2].y, acc[i][1]);
                acc[i][2] = fmaf(pa[i].z, vb[2].z, acc[i][2]);
                acc[i][3] = fmaf(pa[i].z, vb[2].w, acc[i][3]);
                acc[i][0] = fmaf(pa[i].w, vb[3].x, acc[i][0]);
                acc[i][1] = fmaf(pa[i].w, vb[3].y, acc[i][1]);
                acc[i][2] = fmaf(pa[i].w, vb[3].z, acc[i][2]);
                acc[i][3] = fmaf(pa[i].w, vb[3].w, acc[i][3]);
            }
        }
    }

    // Finalize with masked-to-zero correction:
    // m_f = max(m, 0); Z = l*exp(m-m_f) + (S-1-q)*exp(-m_f)
    // z = (acc*exp(m-m_f) + exp(-m_f)*vsuf[q]) / Z
#pragma unroll
    for (int i = 0; i < 4; i++) {
        int qg = q0 + ty * 4 + i;
        float mf = fmaxf(m_i[i], 0.f);
        float corr = __expf(m_i[i] - mf);
        float e = __expf(-mf);
        float lf = l_i[i] * corr + (float)(S_ - 1 - qg) * e;
        float inv = 1.f / lf;
        float4 vs = *(const float4*)&gvs[idx(qg, tx * 4)];
        float4 o;
        o.x = (acc[i][0] * corr + e * vs.x) * inv;
        o.y = (acc[i][1] * corr + e * vs.y) * inv;
        o.z = (acc[i][2] * corr + e * vs.z) * inv;
        o.w = (acc[i][3] * corr + e * vs.w) * inv;
        *(float4*)&gz[idx(qg, tx * 4)] = o;
    }
}

// ---------------------------------------------------------------------------
extern "C" void kernel_launch(void* const* d_in, const int* in_sizes, int n_in,
                              void* d_out, int out_size)
{
    (void)in_sizes; (void)n_in; (void)out_size;
    const float* x   = (const float*)d_in[0];
    const float* W_Q = (const float*)d_in[1];
    const float* b_Q = (const float*)d_in[2];
    const float* W_K = (const float*)d_in[3];
    const float* b_K = (const float*)d_in[4];
    const float* W_V = (const float*)d_in[5];
    const float* b_V = (const float*)d_in[6];
    const float* W_O = (const float*)d_in[7];
    const float* b_O = (const float*)d_in[8];
    float* out = (float*)d_out;

    float *q, *k, *v, *vs, *z;
    cudaGetSymbolAddress((void**)&q,  g_q);
    cudaGetSymbolAddress((void**)&k,  g_k);
    cudaGetSymbolAddress((void**)&v,  g_v);
    cudaGetSymbolAddress((void**)&vs, g_vsuf);
    cudaGetSymbolAddress((void**)&z,  g_z);

    dim3 ggrid(M_ / 128, DM_ / 128);
    sgemm_bias<<<ggrid, 256>>>(x, W_Q, b_Q, q, 0);
    sgemm_bias<<<ggrid, 256>>>(x, W_K, b_K, k, 0);
    sgemm_bias<<<ggrid, 256>>>(x, W_V, b_V, v, 0);

    vsuf_kernel<<<B_ * H_, 512>>>(v, vs);

    const int smem_bytes = 4 * 64 * 68 * sizeof(float);  // 69632
    cudaFuncSetAttribute(flash_attn, cudaFuncAttributeMaxDynamicSharedMemorySize, smem_bytes);
    flash_attn<<<dim3(S_ / 64, B_ * H_), 256, smem_bytes>>>(q, k, v, vs, z);

    sgemm_bias<<<ggrid, 256>>>(z, W_O, b_O, out, 1);
}

// round 5
// speedup vs baseline: 1.2880x; 1.2880x over previous
#include <cuda_runtime.h>
#include <cuda_bf16.h>
#include <cstdint>

// Problem constants
#define B_   2
#define S_   2048
#define H_   16
#define DH_  64
#define DM_  1024
#define M_   (B_ * S_)          // 4096 rows

typedef unsigned long long u64;

// Packed fp32x2 ops (Blackwell sm_100+; SASS FFMA2 — only reachable via PTX)
#define FFMA2(d, a, b) \
    asm("fma.rn.f32x2 %0, %1, %2, %0;" : "+l"(d) : "l"(a), "l"(b))
#define MUL2(d, a, b) \
    asm("mul.rn.f32x2 %0, %1, %2;" : "=l"(d) : "l"(a), "l"(b))
#define PACK2(d, x) \
    asm("mov.b64 %0, {%1, %1};" : "=l"(d) : "r"(__float_as_uint(x)))

__device__ __forceinline__ float lo_f(u64 v) { return __uint_as_float((unsigned)v); }
__device__ __forceinline__ float hi_f(u64 v) { return __uint_as_float((unsigned)(v >> 32)); }

// Scratch (device globals; allocation-free rule)
__device__ float g_q[M_ * DM_];
__device__ float g_k[M_ * DM_];
__device__ float g_v[M_ * DM_];
__device__ float g_vsuf[M_ * DM_];
__device__ float g_z[M_ * DM_];

// ---------------------------------------------------------------------------
// SGEMM: C[M,1024] = A[M,1024] * B + bias. 128x128x8 tile, 8x8/thread,
// packed f32x2 accumulation (pairs over j), double-buffered smem.
// mode 0: B(k,n) at W[(n>>6)*65536 + k*64 + (n&63)]   (QKV weights [H,DM,DH])
// mode 1: B(k,n) at W[k*1024 + n]                     (W_O [H*DH, DM])
// ---------------------------------------------------------------------------
__global__ __launch_bounds__(256)
void sgemm_bias(const float* __restrict__ A, const float* __restrict__ Bw,
                const float* __restrict__ bias, float* __restrict__ C, int mode)
{
    __shared__ float As[2][8][132];
    __shared__ float Bs[2][8][128];

    const int m0 = blockIdx.x * 128;
    const int n0 = blockIdx.y * 128;
    const int t  = threadIdx.x;
    const int ty = t >> 4, tx = t & 15;

    u64 acc2[8][4];
#pragma unroll
    for (int i = 0; i < 8; i++)
#pragma unroll
        for (int j = 0; j < 4; j++) acc2[i][j] = 0ull;

    const int am = t >> 1;          // 0..127
    const int ak = (t & 1) * 4;     // 0 or 4
    const int bk = t >> 5;          // 0..7
    const int bn = (t & 31) * 4;    // 0..124
    const float* Aptr = A + (size_t)(m0 + am) * 1024 + ak;
    const int nb = n0 + bn;

    auto baddr = [&](int k0) -> size_t {
        if (mode == 0) return (size_t)(nb >> 6) * 65536 + (size_t)(k0 + bk) * 64 + (nb & 63);
        return (size_t)(k0 + bk) * 1024 + nb;
    };

    // Prologue: tile 0 -> buffer 0
    {
        float4 av = *(const float4*)(Aptr + 0);
        float4 bv = *(const float4*)(Bw + baddr(0));
        As[0][ak + 0][am] = av.x;
        As[0][ak + 1][am] = av.y;
        As[0][ak + 2][am] = av.z;
        As[0][ak + 3][am] = av.w;
        *(float4*)&Bs[0][bk][bn] = bv;
    }
    __syncthreads();

    int buf = 0;
    for (int k0 = 0; k0 < 1024; k0 += 8) {
        float4 av_n, bv_n;
        const bool more = (k0 + 8) < 1024;
        if (more) {
            av_n = *(const float4*)(Aptr + k0 + 8);
            bv_n = *(const float4*)(Bw + baddr(k0 + 8));
        }

#pragma unroll
        for (int kk = 0; kk < 8; kk++) {
            float4 a0 = *(float4*)&As[buf][kk][ty * 8];
            float4 a1 = *(float4*)&As[buf][kk][ty * 8 + 4];
            ulonglong2 b01 = *(ulonglong2*)&Bs[buf][kk][tx * 8];
            ulonglong2 b23 = *(ulonglong2*)&Bs[buf][kk][tx * 8 + 4];
            float a[8] = {a0.x, a0.y, a0.z, a0.w, a1.x, a1.y, a1.z, a1.w};
#pragma unroll
            for (int i = 0; i < 8; i++) {
                u64 pa;
                PACK2(pa, a[i]);
                FFMA2(acc2[i][0], pa, b01.x);
                FFMA2(acc2[i][1], pa, b01.y);
                FFMA2(acc2[i][2], pa, b23.x);
                FFMA2(acc2[i][3], pa, b23.y);
            }
        }

        if (more) {
            int nb2 = buf ^ 1;
            As[nb2][ak + 0][am] = av_n.x;
            As[nb2][ak + 1][am] = av_n.y;
            As[nb2][ak + 2][am] = av_n.z;
            As[nb2][ak + 3][am] = av_n.w;
            *(float4*)&Bs[nb2][bk][bn] = bv_n;
            __syncthreads();
            buf = nb2;
        }
    }

    float bb[8];
#pragma unroll
    for (int j = 0; j < 8; j++) bb[j] = bias[n0 + tx * 8 + j];

#pragma unroll
    for (int i = 0; i < 8; i++) {
        int row = m0 + ty * 8 + i;
        float* Crow = C + (size_t)row * 1024 + n0 + tx * 8;
        float4 o0 = {lo_f(acc2[i][0]) + bb[0], hi_f(acc2[i][0]) + bb[1],
                     lo_f(acc2[i][1]) + bb[2], hi_f(acc2[i][1]) + bb[3]};
        float4 o1 = {lo_f(acc2[i][2]) + bb[4], hi_f(acc2[i][2]) + bb[5],
                     lo_f(acc2[i][3]) + bb[6], hi_f(acc2[i][3]) + bb[7]};
        *(float4*)(Crow)     = o0;
        *(float4*)(Crow + 4) = o1;
    }
}

// ---------------------------------------------------------------------------
// V suffix sum: vsuf[b,q,h,d] = sum_{k>q} v[b,k,h,d]
// ---------------------------------------------------------------------------
__global__ __launch_bounds__(512)
void vsuf_kernel(const float* __restrict__ v, float* __restrict__ vsuf)
{
    __shared__ float sums[8][64];
    const int bh = blockIdx.x;
    const int b = bh >> 4, h = bh & 15;
    const int d = threadIdx.x & 63;
    const int c = threadIdx.x >> 6;       // 0..7
    const int L = S_ / 8;                 // 256
    const int lo = c * L;

    auto idx = [&](int s) { return ((size_t)(b * S_ + s) * H_ + h) * DH_ + d; };

    float s = 0.f;
    for (int q = lo; q < lo + L; q++) s += v[idx(q)];
    sums[c][d] = s;
    __syncthreads();

    float off = 0.f;
    for (int cc = c + 1; cc < 8; cc++) off += sums[cc][d];

    float run = off;
    for (int q = lo + L - 1; q >= lo; q--) {
        vsuf[idx(q)] = run;
        run += v[idx(q)];
    }
}

// ---------------------------------------------------------------------------
// Flash attention (fp32, packed f32x2) with masked-to-ZERO softmax semantics.
// Block: 64 q-rows of one (b,h). 256 threads (16x16).
// QK: score cols mapped j -> tx + 16*j (2-way Ks conflicts, conflict-free Ps
//     stores), packed accumulation over d.
// PV: original col layout tx*4+j, packed accumulation over j.
// ---------------------------------------------------------------------------
__global__ __launch_bounds__(256)
void flash_attn(const float* __restrict__ gq, const float* __restrict__ gk,
                const float* __restrict__ gv, const float* __restrict__ gvs,
                float* __restrict__ gz)
{
    extern __shared__ float sm[];
    float (*Qs)[68] = (float(*)[68])(sm);
    float (*Ks)[68] = (float(*)[68])(sm + 64 * 68);
    float (*Vs)[68] = (float(*)[68])(sm + 2 * 64 * 68);
    float (*Ps)[68] = (float(*)[68])(sm + 3 * 64 * 68);

    const int qt = blockIdx.x;
    const int bh = blockIdx.y;
    const int b = bh >> 4, h = bh & 15;
    const int q0 = qt * 64;
    const int t = threadIdx.x, ty = t >> 4, tx = t & 15;

    auto idx = [&](int s, int d) { return ((size_t)(b * S_ + s) * H_ + h) * DH_ + d; };

    const float scale = 0.125f;  // 1/sqrt(64)
    for (int i = t; i < 64 * 16; i += 256) {
        int r = i >> 4, c4 = (i & 15) * 4;
        float4 v = *(const float4*)&gq[idx(q0 + r, c4)];
        v.x *= scale; v.y *= scale; v.z *= scale; v.w *= scale;
        *(float4*)&Qs[r][c4] = v;
    }

    float m_i[4], l_i[4];
    u64 acc2[4][2];
#pragma unroll
    for (int i = 0; i < 4; i++) {
        m_i[i] = -1e30f; l_i[i] = 0.f;
        acc2[i][0] = 0ull; acc2[i][1] = 0ull;
    }

    for (int kt = 0; kt <= qt; kt++) {
        const int k0 = kt * 64;
        __syncthreads();
        for (int i = t; i < 64 * 16; i += 256) {
            int r = i >> 4, c4 = (i & 15) * 4;
            *(float4*)&Ks[r][c4] = *(const float4*)&gk[idx(k0 + r, c4)];
            *(float4*)&Vs[r][c4] = *(const float4*)&gv[idx(k0 + r, c4)];
        }
        __syncthreads();

        // ---- QK^T: packed over d ----
        u64 s2[4][4];
#pragma unroll
        for (int i = 0; i < 4; i++)
#pragma unroll
            for (int j = 0; j < 4; j++) s2[i][j] = 0ull;

#pragma unroll
        for (int d = 0; d < 64; d += 4) {
            ulonglong2 qa[4], ka[4];
#pragma unroll
            for (int i = 0; i < 4; i++) qa[i] = *(ulonglong2*)&Qs[ty * 4 + i][d];
#pragma unroll
            for (int j = 0; j < 4; j++) ka[j] = *(ulonglong2*)&Ks[tx + 16 * j][d];
#pragma unroll
            for (int i = 0; i < 4; i++)
#pragma unroll
                for (int j = 0; j < 4; j++) {
                    FFMA2(s2[i][j], qa[i].x, ka[j].x);
                    FFMA2(s2[i][j], qa[i].y, ka[j].y);
                }
        }

        float s[4][4];
#pragma unroll
        for (int i = 0; i < 4; i++)
#pragma unroll
            for (int j = 0; j < 4; j++) s[i][j] = lo_f(s2[i][j]) + hi_f(s2[i][j]);

        if (kt == qt) {
#pragma unroll
            for (int i = 0; i < 4; i++)
#pragma unroll
                for (int j = 0; j < 4; j++)
                    if (k0 + tx + 16 * j > q0 + ty * 4 + i) s[i][j] = -1e30f;
        }

        // ---- online softmax (rows i, reduce over 16 lanes) ----
#pragma unroll
        for (int i = 0; i < 4; i++) {
            float mt = fmaxf(fmaxf(s[i][0], s[i][1]), fmaxf(s[i][2], s[i][3]));
#pragma unroll
            for (int off = 8; off >= 1; off >>= 1)
                mt = fmaxf(mt, __shfl_xor_sync(0xffffffffu, mt, off, 16));
            float mnew = fmaxf(m_i[i], mt);
            float rs = 0.f;
#pragma unroll
            for (int j = 0; j < 4; j++) {
                float p = __expf(s[i][j] - mnew);
                s[i][j] = p;
                rs += p;
            }
#pragma unroll
            for (int off = 8; off >= 1; off >>= 1)
                rs += __shfl_xor_sync(0xffffffffu, rs, off, 16);
            float corr = __expf(m_i[i] - mnew);
            l_i[i] = l_i[i] * corr + rs;
            m_i[i] = mnew;
            u64 c2;
            PACK2(c2, corr);
            MUL2(acc2[i][0], acc2[i][0], c2);
            MUL2(acc2[i][1], acc2[i][1], c2);
#pragma unroll
            for (int j = 0; j < 4; j++) Ps[ty * 4 + i][tx + 16 * j] = s[i][j];
        }
        __syncthreads();

        // ---- PV: packed over j (output cols tx*4 .. tx*4+3) ----
#pragma unroll
        for (int kk = 0; kk < 64; kk += 4) {
            float4 pa[4];
            ulonglong2 vb[4];
#pragma unroll
            for (int i = 0; i < 4; i++) pa[i] = *(float4*)&Ps[ty * 4 + i][kk];
#pragma unroll
            for (int u = 0; u < 4; u++) vb[u] = *(ulonglong2*)&Vs[kk + u][tx * 4];
#pragma unroll
            for (int i = 0; i < 4; i++) {
                u64 pp;
                PACK2(pp, pa[i].x);
                FFMA2(acc2[i][0], pp, vb[0].x);
                FFMA2(acc2[i][1], pp, vb[0].y);
                PACK2(pp, pa[i].y);
                FFMA2(acc2[i][0], pp, vb[1].x);
                FFMA2(acc2[i][1], pp, vb[1].y);
                PACK2(pp, pa[i].z);
                FFMA2(acc2[i][0], pp, vb[2].x);
                FFMA2(acc2[i][1], pp, vb[2].y);
                PACK2(pp, pa[i].w);
                FFMA2(acc2[i][0], pp, vb[3].x);
                FFMA2(acc2[i][1], pp, vb[3].y);
            }
        }
    }

    // Finalize with masked-to-zero correction:
    // m_f = max(m, 0); Z = l*exp(m-m_f) + (S-1-q)*exp(-m_f)
    // z = (acc*exp(m-m_f) + exp(-m_f)*vsuf[q]) / Z
#pragma unroll
    for (int i = 0; i < 4; i++) {
        int qg = q0 + ty * 4 + i;
        float mf = fmaxf(m_i[i], 0.f);
        float corr = __expf(m_i[i] - mf);
        float e = __expf(-mf);
        float lf = l_i[i] * corr + (float)(S_ - 1 - qg) * e;
        float inv = 1.f / lf;
        float4 vs = *(const float4*)&gvs[idx(qg, tx * 4)];
        float4 o;
        o.x = (lo_f(acc2[i][0]) * corr + e * vs.x) * inv;
        o.y = (hi_f(acc2[i][0]) * corr + e * vs.y) * inv;
        o.z = (lo_f(acc2[i][1]) * corr + e * vs.z) * inv;
        o.w = (hi_f(acc2[i][1]) * corr + e * vs.w) * inv;
        *(float4*)&gz[idx(qg, tx * 4)] = o;
    }
}

// ---------------------------------------------------------------------------
extern "C" void kernel_launch(void* const* d_in, const int* in_sizes, int n_in,
                              void* d_out, int out_size)
{
    (void)in_sizes; (void)n_in; (void)out_size;
    const float* x   = (const float*)d_in[0];
    const float* W_Q = (const float*)d_in[1];
    const float* b_Q = (const float*)d_in[2];
    const float* W_K = (const float*)d_in[3];
    const float* b_K = (const float*)d_in[4];
    const float* W_V = (const float*)d_in[5];
    const float* b_V = (const float*)d_in[6];
    const float* W_O = (const float*)d_in[7];
    const float* b_O = (const float*)d_in[8];
    float* out = (float*)d_out;

    float *q, *k, *v, *vs, *z;
    cudaGetSymbolAddress((void**)&q,  g_q);
    cudaGetSymbolAddress((void**)&k,  g_k);
    cudaGetSymbolAddress((void**)&v,  g_v);
    cudaGetSymbolAddress((void**)&vs, g_vsuf);
    cudaGetSymbolAddress((void**)&z,  g_z);

    dim3 ggrid(M_ / 128, DM_ / 128);
    sgemm_bias<<<ggrid, 256>>>(x, W_Q, b_Q, q, 0);
    sgemm_bias<<<ggrid, 256>>>(x, W_K, b_K, k, 0);
    sgemm_bias<<<ggrid, 256>>>(x, W_V, b_V, v, 0);

    vsuf_kernel<<<B_ * H_, 512>>>(v, vs);

    const int smem_bytes = 4 * 64 * 68 * sizeof(float);  // 69632
    cudaFuncSetAttribute(flash_attn, cudaFuncAttributeMaxDynamicSharedMemorySize, smem_bytes);
    flash_attn<<<dim3(S_ / 64, B_ * H_), 256, smem_bytes>>>(q, k, v, vs, z);

    sgemm_bias<<<ggrid, 256>>>(z, W_O, b_O, out, 1);
}